// round 13
// baseline (speedup 1.0000x reference)
#include <cuda_runtime.h>
#include <cuda_bf16.h>
#include <stdint.h>

#define FULLMASK 0xFFFFFFFFu

constexpr int HWN     = 3136;   // 56*56
constexpr int NCH     = 512;
constexpr int NBATCH  = 32;
constexpr int CPB     = 4;      // channels per block (4 warps per channel)
constexpr int KSEL    = 627;    // round(0.2*3136)
constexpr int RBRANK  = HWN - KSEL + 1;  // bottom-end rank from largest
constexpr int STRIDE  = 3140;   // smem row stride (u32), 16B aligned
constexpr int NQ      = HWN / 4;        // 784 uint4 per row
constexpr int QQ      = NQ / 4;         // 196 uint4 per warp quarter
constexpr int QELEM   = QQ * 4;         // 784 elements per quarter
constexpr int HSTR    = 1552;   // 1024 (L0 hist) + 256 (bufA) + 256 (bufB) + 16 spare
constexpr int SMEM_WORDS = CPB * STRIDE + CPB * HSTR;
constexpr float ALPHA = 0.7f;

__device__ __forceinline__ float key2f(unsigned u) {
    return __uint_as_float((u & 0x80000000u) ? (u & 0x7FFFFFFFu) : ~u);
}
// branch-free monotone key from float bits
__device__ __forceinline__ unsigned mkey(unsigned b) {
    return b ^ ((unsigned)(((int)b) >> 31) | 0x80000000u);
}

__device__ __forceinline__ float wredf(float v) {
#pragma unroll
    for (int d = 16; d; d >>= 1) v += __shfl_xor_sync(FULLMASK, v, d);
    return v;
}

// per-channel barrier: 4 warps (128 threads), barrier id = channel+1
__device__ __forceinline__ void chbar(int id) {
    asm volatile("bar.sync %0, %1;" :: "r"(id), "r"(128) : "memory");
}

// ---- 1024-bin u32 walk, two-stage. rank r is 1-based FROM THE LARGEST bin.
// Returns (bin, rankInBin, countOfBin).
__device__ __forceinline__ int3 walk1024(const unsigned* h, int lane, int r)
{
    // stage 1: per-lane totals over 32 consecutive bins
    int s = 0;
#pragma unroll
    for (int j = 0; j < 32; j++) s += (int)h[lane * 32 + j];
    int incl = s;                            // suffix sum over lanes >= lane
#pragma unroll
    for (int d = 1; d < 32; d <<= 1) {
        int v = __shfl_down_sync(FULLMASK, incl, d);
        if (lane + d < 32) incl += v;
    }
    int hi = incl - s;                       // count in larger-bin lanes
    bool sel = (hi < r) && (r <= hi + s);
    unsigned bal = __ballot_sync(FULLMASK, sel);
    int L = __ffs((int)bal) - 1;
    int rloc = __shfl_sync(FULLMASK, r - hi, L);
    // stage 2: cooperative scan of lane L's 32 bins (one bin per lane)
    int c2 = (int)h[L * 32 + lane];
    int incl2 = c2;
#pragma unroll
    for (int d = 1; d < 32; d <<= 1) {
        int v = __shfl_down_sync(FULLMASK, incl2, d);
        if (lane + d < 32) incl2 += v;
    }
    int hi2 = incl2 - c2;
    bool sel2 = (hi2 < rloc) && (rloc <= hi2 + c2);
    unsigned bal2 = __ballot_sync(FULLMASK, sel2);
    int L2 = __ffs((int)bal2) - 1;
    int bin = L * 32 + L2;
    int rr  = __shfl_sync(FULLMASK, rloc - hi2, L2);
    int cc  = __shfl_sync(FULLMASK, c2, L2);
    return make_int3(bin, rr, cc);
}

// ---- 256-bin packed walk (low16/high16 selected by shift). rank from largest.
__device__ __forceinline__ int3 walk(const unsigned* hist, int shift, int lane, int r)
{
    unsigned c[8];
    int s = 0;
#pragma unroll
    for (int j = 0; j < 8; j++) {
        c[j] = (hist[lane * 8 + j] >> shift) & 0xFFFFu;
        s += (int)c[j];
    }
    int incl = s;
#pragma unroll
    for (int d = 1; d < 32; d <<= 1) {
        int v = __shfl_down_sync(FULLMASK, incl, d);
        if (lane + d < 32) incl += v;
    }
    int hi = incl - s;
    bool sel = (hi < r) && (r <= hi + s);
    unsigned bal = __ballot_sync(FULLMASK, sel);
    int L = __ffs((int)bal) - 1;
    int bin = -1, rr = 0, cc = 0;
    if (lane == L) {
        int rloc = r - hi, cum = 0;
#pragma unroll
        for (int j = 7; j >= 0; j--) {
            if (bin < 0 && rloc <= cum + (int)c[j]) { bin = j; rr = rloc - cum; cc = (int)c[j]; }
            cum += (int)c[j];
        }
        bin += lane * 8;
    }
    bin = __shfl_sync(FULLMASK, bin, L);
    rr  = __shfl_sync(FULLMASK, rr,  L);
    cc  = __shfl_sync(FULLMASK, cc,  L);
    return make_int3(bin, rr, cc);
}

extern __shared__ unsigned smem[];

__global__ void __launch_bounds__(512, 3)
wildcat_kernel(const float* __restrict__ x, float* __restrict__ out)
{
    unsigned* vals = smem;                   // CPB * STRIDE (raw float bits)
    unsigned* hist = smem + CPB * STRIDE;    // CPB * HSTR

    const int t    = threadIdx.x;
    const int lane = t & 31;
    const int warp = t >> 5;                 // 0..15
    const int w    = warp >> 2;              // channel 0..3
    const int q    = warp & 3;               // quarter of the spatial row
    const int bar  = w + 1;                  // named barrier id for this channel
    const int b    = blockIdx.x >> 7;        // batch
    const int c0   = (blockIdx.x & 127) * CPB;

    for (int i = t; i < CPB * HSTR; i += 512) hist[i] = 0;
    __syncthreads();

    // ---- load + transpose + FUSED 10-bit L0 histogram (raw atomics) --------
    // 1024 bins => within-warp same-bin collisions are rare; no match needed.
    {
        const float4* src = reinterpret_cast<const float4*>(
            x + (size_t)b * HWN * NCH + c0);
#pragma unroll 2
        for (int i = 0; i < 6; i++) {        // 6 full, unconditional iterations
            int hw = t + i * 512;
            float4 v = src[(size_t)hw * (NCH / 4)];
            unsigned k[4] = { __float_as_uint(v.x), __float_as_uint(v.y),
                              __float_as_uint(v.z), __float_as_uint(v.w) };
            vals[0 * STRIDE + hw] = k[0];
            vals[1 * STRIDE + hw] = k[1];
            vals[2 * STRIDE + hw] = k[2];
            vals[3 * STRIDE + hw] = k[3];
#pragma unroll
            for (int e = 0; e < 4; e++)
                atomicAdd(&hist[e * HSTR + (mkey(k[e]) >> 22)], 1u);
        }
        if (warp < 2) {                      // tail: hw in [3072, 3136), fully valid
            int hw = t + 3072;
            float4 v = src[(size_t)hw * (NCH / 4)];
            unsigned k[4] = { __float_as_uint(v.x), __float_as_uint(v.y),
                              __float_as_uint(v.z), __float_as_uint(v.w) };
            vals[0 * STRIDE + hw] = k[0];
            vals[1 * STRIDE + hw] = k[1];
            vals[2 * STRIDE + hw] = k[2];
            vals[3 * STRIDE + hw] = k[3];
#pragma unroll
            for (int e = 0; e < 4; e++)
                atomicAdd(&hist[e * HSTR + (mkey(k[e]) >> 22)], 1u);
        }
    }
    __syncthreads();                         // last block-wide barrier

    // ---- per-channel selection (channels decoupled from here) --------------
    unsigned* rowU  = vals + w * STRIDE;
    const uint4* row4 = reinterpret_cast<const uint4*>(rowU);
    unsigned* h0    = hist + w * HSTR;       // 1024-bin L0
    unsigned* bufA  = h0 + 1024;             // 256
    unsigned* bufB  = bufA + 256;            // 256
    unsigned* spare = bufB + 256;            // 16
    const int qBase = q * QQ;
    const int eBase = q * QELEM;

    int rT = 0;                              // live in q0
    int rB = 0;                              // live in q1

    // L0 walks: top on q0, bottom on q1
    if (q == 0) {
        int3 st = walk1024(h0, lane, KSEL);
        rT = st.y;
        if (lane == 0) spare[0] = (unsigned)st.x;
    } else if (q == 1) {
        int3 sb = walk1024(h0, lane, RBRANK);
        rB = sb.y;
        if (lane == 0) spare[1] = (unsigned)sb.x;
    }
    chbar(bar);
    const int selT = (int)spare[0];          // 10-bit bins
    const int selB = (int)spare[1];

    // ---- L1: single full scan: sure-sums + compaction + hist(B, bits 21..14)
    float sg = 0.f, sl = 0.f;
    unsigned cnt = 0;                        // compacted count (warp-uniform)
#pragma unroll 1
    for (int i = 0; i < 7; i++) {
        const bool tailIt = (i == 6);
        const bool valid = !tailIt || (lane < QQ - 192);
        uint4 kv = valid ? row4[qBase + i * 32 + lane] : make_uint4(0u, 0u, 0u, 0u);
        unsigned ks[4] = {kv.x, kv.y, kv.z, kv.w};
#pragma unroll
        for (int e = 0; e < 4; e++) {
            unsigned bb = ks[e];
            unsigned kk = mkey(bb);
            int bin = (int)(kk >> 22);
            float v = __uint_as_float(bb);
            if (valid && bin > selT) sg += v;
            if (valid && bin < selB) sl += v;
            unsigned add = (valid && bin == selT ? 1u : 0u)
                         + (valid && bin == selB ? 0x10000u : 0u);
            if (add) atomicAdd(&bufB[(kk >> 14) & 0xFFu], add);
            unsigned bal = __ballot_sync(FULLMASK, add != 0u);
            if (add) {
                unsigned pos = cnt + __popc(bal & ((1u << lane) - 1u));
                rowU[eBase + pos] = bb;      // pos < read frontier: in-warp safe
            }
            cnt += (unsigned)__popc(bal);
        }
    }
    chbar(bar);

    // L1 walks (q0 top / q1 bottom) overlapped with zeroing bufA (q2/q3)
    if (q == 0) {
        int3 wt = walk(bufB, 0, lane, rT);
        rT = wt.y;
        if (lane == 0) spare[2] = ((unsigned)selT << 22) | ((unsigned)wt.x << 14);
    } else if (q == 1) {
        int3 wb = walk(bufB, 16, lane, rB);
        rB = wb.y;
        if (lane == 0) spare[3] = ((unsigned)selB << 22) | ((unsigned)wb.x << 14);
    } else {
        for (int i = (q - 2) * 32 + lane; i < 256; i += 64) bufA[i] = 0;
    }
    chbar(bar);
    unsigned pfxT = spare[2], pfxB = spare[3];
    const int citers = (int)((cnt + 31u) >> 5);

    // ---- L2 over compact list (hist A, bits 13..6) --------------------------
#pragma unroll 1
    for (int i = 0; i < citers; i++) {
        unsigned idx = (unsigned)(i * 32 + lane);
        if (idx < cnt) {
            unsigned kk = mkey(rowU[eBase + idx]);
            unsigned hi18 = kk >> 14;
            unsigned add = ((hi18 == (pfxT >> 14)) ? 1u : 0u)
                         + ((hi18 == (pfxB >> 14)) ? 0x10000u : 0u);
            if (add) atomicAdd(&bufA[(kk >> 6) & 0xFFu], add);
        }
    }
    chbar(bar);

    if (q == 0) {
        int3 wt = walk(bufA, 0, lane, rT);
        rT = wt.y;
        if (lane == 0) spare[2] = pfxT | ((unsigned)wt.x << 6);
    } else if (q == 1) {
        int3 wb = walk(bufA, 16, lane, rB);
        rB = wb.y;
        if (lane == 0) spare[3] = pfxB | ((unsigned)wb.x << 6);
    } else {
        for (int i = (q - 2) * 32 + lane; i < 256; i += 64) bufB[i] = 0;
    }
    chbar(bar);
    pfxT = spare[2]; pfxB = spare[3];

    // ---- L3 over compact list (hist B, bits 5..0 -> 64 bins) ----------------
#pragma unroll 1
    for (int i = 0; i < citers; i++) {
        unsigned idx = (unsigned)(i * 32 + lane);
        if (idx < cnt) {
            unsigned kk = mkey(rowU[eBase + idx]);
            unsigned hi26 = kk >> 6;
            unsigned add = ((hi26 == (pfxT >> 6)) ? 1u : 0u)
                         + ((hi26 == (pfxB >> 6)) ? 0x10000u : 0u);
            if (add) atomicAdd(&bufB[kk & 0x3Fu], add);
        }
    }
    chbar(bar);

    if (q == 0) {
        int3 wt = walk(bufB, 0, lane, rT);   // bins 64..255 are zero: harmless
        if (lane == 0) {
            spare[4] = __float_as_uint(key2f(pfxT | (unsigned)wt.x));
            spare[6] = (unsigned)wt.y;           // rT3
        }
    } else if (q == 1) {
        int3 wb = walk(bufB, 16, lane, rB);
        if (lane == 0) {
            spare[5] = __float_as_uint(key2f(pfxB | (unsigned)wb.x));
            spare[7] = (unsigned)(wb.y - wb.z);  // rB3 - eqB (signed)
        }
    }
    chbar(bar);
    const float vT = __uint_as_float(spare[4]);
    const float vB = __uint_as_float(spare[5]);

    // ---- stats tail over compact list (float compares) ---------------------
#pragma unroll 1
    for (int i = 0; i < citers; i++) {
        unsigned idx = (unsigned)(i * 32 + lane);
        if (idx < cnt) {
            float v = __uint_as_float(rowU[eBase + idx]);
            if (v > vT) sg += v;
            if (v < vB) sl += v;
        }
    }
    sg = wredf(sg);
    sl = wredf(sl);

    float* accF = reinterpret_cast<float*>(spare + 8);
    if (lane == 0) {
        atomicAdd(&accF[0], sg);
        atomicAdd(&accF[1], sl);
    }
    chbar(bar);

    if (q == 0 && lane == 0) {
        int rT3  = (int)spare[6];
        int rbme = (int)spare[7];            // rB3 - eqB (signed)
        int cg   = KSEL - rT3;               // strictly > vT
        int cl   = HWN - RBRANK + rbme;      // strictly < vB
        float Sg = accF[0], Sl = accF[1];
        float xmax = (Sg + (float)(KSEL - cg) * vT) * (1.0f / (float)KSEL);
        float xmin = (Sl + (float)(KSEL - cl) * vB) * (ALPHA / (float)KSEL);
        out[b * NCH + c0 + w] = 0.5f * (xmax + xmin);
    }
}

extern "C" void kernel_launch(void* const* d_in, const int* in_sizes, int n_in,
                              void* d_out, int out_size)
{
    const float* x = (const float*)d_in[0];
    float* out = (float*)d_out;
    cudaFuncSetAttribute(wildcat_kernel,
                         cudaFuncAttributeMaxDynamicSharedMemorySize,
                         SMEM_WORDS * (int)sizeof(unsigned));
    wildcat_kernel<<<NBATCH * (NCH / CPB), 512, SMEM_WORDS * sizeof(unsigned)>>>(x, out);
}

// round 14
// speedup vs baseline: 1.0934x; 1.0934x over previous
#include <cuda_runtime.h>
#include <cuda_bf16.h>
#include <stdint.h>

#define FULLMASK 0xFFFFFFFFu

constexpr int HWN     = 3136;   // 56*56
constexpr int NCH     = 512;
constexpr int NBATCH  = 32;
constexpr int CPB     = 4;      // channels per block (4 warps per channel)
constexpr int KSEL    = 627;    // round(0.2*3136)
constexpr int RBRANK  = HWN - KSEL + 1;  // bottom-end rank from largest
constexpr int STRIDE  = 3140;   // smem row stride (u32), 16B aligned
constexpr int NQ      = HWN / 4;        // 784 uint4 per row
constexpr int QQ      = NQ / 4;         // 196 uint4 per warp quarter
constexpr int QELEM   = QQ * 4;         // 784 elements per quarter
constexpr int H0SZ    = 1056;   // 1024 bins padded to 33-word groups (bank-conflict-free walk)
constexpr int HSTR    = H0SZ + 256 + 256 + 16;   // L0 + bufA + bufB + spare = 1584
constexpr int SMEM_WORDS = CPB * STRIDE + CPB * HSTR;
constexpr float ALPHA = 0.7f;

__device__ __forceinline__ float key2f(unsigned u) {
    return __uint_as_float((u & 0x80000000u) ? (u & 0x7FFFFFFFu) : ~u);
}
// branch-free monotone key from float bits
__device__ __forceinline__ unsigned mkey(unsigned b) {
    return b ^ ((unsigned)(((int)b) >> 31) | 0x80000000u);
}
// padded physical index for the 1024-bin L0 histogram
__device__ __forceinline__ int h0idx(unsigned bin) {
    return (int)(bin + (bin >> 5));
}

__device__ __forceinline__ float wredf(float v) {
#pragma unroll
    for (int d = 16; d; d >>= 1) v += __shfl_xor_sync(FULLMASK, v, d);
    return v;
}

// per-channel barrier: 4 warps (128 threads), barrier id = channel+1
__device__ __forceinline__ void chbar(int id) {
    asm volatile("bar.sync %0, %1;" :: "r"(id), "r"(128) : "memory");
}

// ---- 1024-bin u32 walk over PADDED layout (33 words per 32 bins).
// rank r is 1-based FROM THE LARGEST bin. Returns (bin, rankInBin, countOfBin).
__device__ __forceinline__ int3 walk1024(const unsigned* h, int lane, int r)
{
    // stage 1: per-lane totals over 32 consecutive logical bins.
    // physical base lane*33 -> lane*33 % 32 == lane: conflict-free each j.
    const unsigned* hl = h + lane * 33;
    int s = 0;
#pragma unroll
    for (int j = 0; j < 32; j++) s += (int)hl[j];
    int incl = s;                            // suffix sum over lanes >= lane
#pragma unroll
    for (int d = 1; d < 32; d <<= 1) {
        int v = __shfl_down_sync(FULLMASK, incl, d);
        if (lane + d < 32) incl += v;
    }
    int hi = incl - s;                       // count in larger-bin lanes
    bool sel = (hi < r) && (r <= hi + s);
    unsigned bal = __ballot_sync(FULLMASK, sel);
    int L = __ffs((int)bal) - 1;
    int rloc = __shfl_sync(FULLMASK, r - hi, L);
    // stage 2: cooperative scan of lane L's 32 bins (stride-1: conflict-free)
    int c2 = (int)h[L * 33 + lane];
    int incl2 = c2;
#pragma unroll
    for (int d = 1; d < 32; d <<= 1) {
        int v = __shfl_down_sync(FULLMASK, incl2, d);
        if (lane + d < 32) incl2 += v;
    }
    int hi2 = incl2 - c2;
    bool sel2 = (hi2 < rloc) && (rloc <= hi2 + c2);
    unsigned bal2 = __ballot_sync(FULLMASK, sel2);
    int L2 = __ffs((int)bal2) - 1;
    int bin = L * 32 + L2;                   // logical bin
    int rr  = __shfl_sync(FULLMASK, rloc - hi2, L2);
    int cc  = __shfl_sync(FULLMASK, c2, L2);
    return make_int3(bin, rr, cc);
}

// ---- 256-bin packed walk (low16/high16 selected by shift). rank from largest.
__device__ __forceinline__ int3 walk(const unsigned* hist, int shift, int lane, int r)
{
    unsigned c[8];
    int s = 0;
#pragma unroll
    for (int j = 0; j < 8; j++) {
        c[j] = (hist[lane * 8 + j] >> shift) & 0xFFFFu;
        s += (int)c[j];
    }
    int incl = s;
#pragma unroll
    for (int d = 1; d < 32; d <<= 1) {
        int v = __shfl_down_sync(FULLMASK, incl, d);
        if (lane + d < 32) incl += v;
    }
    int hi = incl - s;
    bool sel = (hi < r) && (r <= hi + s);
    unsigned bal = __ballot_sync(FULLMASK, sel);
    int L = __ffs((int)bal) - 1;
    int bin = -1, rr = 0, cc = 0;
    if (lane == L) {
        int rloc = r - hi, cum = 0;
#pragma unroll
        for (int j = 7; j >= 0; j--) {
            if (bin < 0 && rloc <= cum + (int)c[j]) { bin = j; rr = rloc - cum; cc = (int)c[j]; }
            cum += (int)c[j];
        }
        bin += lane * 8;
    }
    bin = __shfl_sync(FULLMASK, bin, L);
    rr  = __shfl_sync(FULLMASK, rr,  L);
    cc  = __shfl_sync(FULLMASK, cc,  L);
    return make_int3(bin, rr, cc);
}

extern __shared__ unsigned smem[];

__global__ void __launch_bounds__(512, 3)
wildcat_kernel(const float* __restrict__ x, float* __restrict__ out)
{
    unsigned* vals = smem;                   // CPB * STRIDE (raw float bits)
    unsigned* hist = smem + CPB * STRIDE;    // CPB * HSTR

    const int t    = threadIdx.x;
    const int lane = t & 31;
    const int warp = t >> 5;                 // 0..15
    const int w    = warp >> 2;              // channel 0..3
    const int q    = warp & 3;               // quarter of the spatial row
    const int bar  = w + 1;                  // named barrier id for this channel
    const int b    = blockIdx.x >> 7;        // batch
    const int c0   = (blockIdx.x & 127) * CPB;

    for (int i = t; i < CPB * HSTR; i += 512) hist[i] = 0;
    __syncthreads();

    // ---- load + transpose + FUSED 10-bit L0 histogram (raw atomics) --------
    // 1024 bins => within-warp same-bin collisions are rare; no match needed.
    {
        const float4* src = reinterpret_cast<const float4*>(
            x + (size_t)b * HWN * NCH + c0);
#pragma unroll 2
        for (int i = 0; i < 6; i++) {        // 6 full, unconditional iterations
            int hw = t + i * 512;
            float4 v = src[(size_t)hw * (NCH / 4)];
            unsigned k[4] = { __float_as_uint(v.x), __float_as_uint(v.y),
                              __float_as_uint(v.z), __float_as_uint(v.w) };
            vals[0 * STRIDE + hw] = k[0];
            vals[1 * STRIDE + hw] = k[1];
            vals[2 * STRIDE + hw] = k[2];
            vals[3 * STRIDE + hw] = k[3];
#pragma unroll
            for (int e = 0; e < 4; e++)
                atomicAdd(&hist[e * HSTR + h0idx(mkey(k[e]) >> 22)], 1u);
        }
        if (warp < 2) {                      // tail: hw in [3072, 3136), fully valid
            int hw = t + 3072;
            float4 v = src[(size_t)hw * (NCH / 4)];
            unsigned k[4] = { __float_as_uint(v.x), __float_as_uint(v.y),
                              __float_as_uint(v.z), __float_as_uint(v.w) };
            vals[0 * STRIDE + hw] = k[0];
            vals[1 * STRIDE + hw] = k[1];
            vals[2 * STRIDE + hw] = k[2];
            vals[3 * STRIDE + hw] = k[3];
#pragma unroll
            for (int e = 0; e < 4; e++)
                atomicAdd(&hist[e * HSTR + h0idx(mkey(k[e]) >> 22)], 1u);
        }
    }
    __syncthreads();                         // last block-wide barrier

    // ---- per-channel selection (channels decoupled from here) --------------
    unsigned* rowU  = vals + w * STRIDE;
    const uint4* row4 = reinterpret_cast<const uint4*>(rowU);
    unsigned* h0    = hist + w * HSTR;       // padded 1024-bin L0
    unsigned* bufA  = h0 + H0SZ;             // 256
    unsigned* bufB  = bufA + 256;            // 256
    unsigned* spare = bufB + 256;            // 16
    const int qBase = q * QQ;
    const int eBase = q * QELEM;

    int rT = 0;                              // live in q0
    int rB = 0;                              // live in q1

    // L0 walks: top on q0, bottom on q1
    if (q == 0) {
        int3 st = walk1024(h0, lane, KSEL);
        rT = st.y;
        if (lane == 0) spare[0] = (unsigned)st.x;
    } else if (q == 1) {
        int3 sb = walk1024(h0, lane, RBRANK);
        rB = sb.y;
        if (lane == 0) spare[1] = (unsigned)sb.x;
    }
    chbar(bar);
    const int selT = (int)spare[0];          // 10-bit logical bins
    const int selB = (int)spare[1];

    // ---- L1: single full scan: sure-sums + compaction + hist(B, bits 21..14)
    float sg = 0.f, sl = 0.f;
    unsigned cnt = 0;                        // compacted count (warp-uniform)
#pragma unroll 1
    for (int i = 0; i < 7; i++) {
        const bool tailIt = (i == 6);
        const bool valid = !tailIt || (lane < QQ - 192);
        uint4 kv = valid ? row4[qBase + i * 32 + lane] : make_uint4(0u, 0u, 0u, 0u);
        unsigned ks[4] = {kv.x, kv.y, kv.z, kv.w};
#pragma unroll
        for (int e = 0; e < 4; e++) {
            unsigned bb = ks[e];
            unsigned kk = mkey(bb);
            int bin = (int)(kk >> 22);
            float v = __uint_as_float(bb);
            if (valid && bin > selT) sg += v;
            if (valid && bin < selB) sl += v;
            unsigned add = (valid && bin == selT ? 1u : 0u)
                         + (valid && bin == selB ? 0x10000u : 0u);
            if (add) atomicAdd(&bufB[(kk >> 14) & 0xFFu], add);
            unsigned bal = __ballot_sync(FULLMASK, add != 0u);
            if (add) {
                unsigned pos = cnt + __popc(bal & ((1u << lane) - 1u));
                rowU[eBase + pos] = bb;      // pos < read frontier: in-warp safe
            }
            cnt += (unsigned)__popc(bal);
        }
    }
    chbar(bar);

    // L1 walks (q0 top / q1 bottom) overlapped with zeroing bufA (q2/q3)
    if (q == 0) {
        int3 wt = walk(bufB, 0, lane, rT);
        rT = wt.y;
        if (lane == 0) spare[2] = ((unsigned)selT << 22) | ((unsigned)wt.x << 14);
    } else if (q == 1) {
        int3 wb = walk(bufB, 16, lane, rB);
        rB = wb.y;
        if (lane == 0) spare[3] = ((unsigned)selB << 22) | ((unsigned)wb.x << 14);
    } else {
        for (int i = (q - 2) * 32 + lane; i < 256; i += 64) bufA[i] = 0;
    }
    chbar(bar);
    unsigned pfxT = spare[2], pfxB = spare[3];
    const int citers = (int)((cnt + 31u) >> 5);

    // ---- L2 over compact list (hist A, bits 13..6) --------------------------
#pragma unroll 1
    for (int i = 0; i < citers; i++) {
        unsigned idx = (unsigned)(i * 32 + lane);
        if (idx < cnt) {
            unsigned kk = mkey(rowU[eBase + idx]);
            unsigned hi18 = kk >> 14;
            unsigned add = ((hi18 == (pfxT >> 14)) ? 1u : 0u)
                         + ((hi18 == (pfxB >> 14)) ? 0x10000u : 0u);
            if (add) atomicAdd(&bufA[(kk >> 6) & 0xFFu], add);
        }
    }
    chbar(bar);

    if (q == 0) {
        int3 wt = walk(bufA, 0, lane, rT);
        rT = wt.y;
        if (lane == 0) spare[2] = pfxT | ((unsigned)wt.x << 6);
    } else if (q == 1) {
        int3 wb = walk(bufA, 16, lane, rB);
        rB = wb.y;
        if (lane == 0) spare[3] = pfxB | ((unsigned)wb.x << 6);
    } else {
        for (int i = (q - 2) * 32 + lane; i < 256; i += 64) bufB[i] = 0;
    }
    chbar(bar);
    pfxT = spare[2]; pfxB = spare[3];

    // ---- L3 over compact list (hist B, bits 5..0 -> 64 bins) ----------------
#pragma unroll 1
    for (int i = 0; i < citers; i++) {
        unsigned idx = (unsigned)(i * 32 + lane);
        if (idx < cnt) {
            unsigned kk = mkey(rowU[eBase + idx]);
            unsigned hi26 = kk >> 6;
            unsigned add = ((hi26 == (pfxT >> 6)) ? 1u : 0u)
                         + ((hi26 == (pfxB >> 6)) ? 0x10000u : 0u);
            if (add) atomicAdd(&bufB[kk & 0x3Fu], add);
        }
    }
    chbar(bar);

    if (q == 0) {
        int3 wt = walk(bufB, 0, lane, rT);   // bins 64..255 are zero: harmless
        if (lane == 0) {
            spare[4] = __float_as_uint(key2f(pfxT | (unsigned)wt.x));
            spare[6] = (unsigned)wt.y;           // rT3
        }
    } else if (q == 1) {
        int3 wb = walk(bufB, 16, lane, rB);
        if (lane == 0) {
            spare[5] = __float_as_uint(key2f(pfxB | (unsigned)wb.x));
            spare[7] = (unsigned)(wb.y - wb.z);  // rB3 - eqB (signed)
        }
    }
    chbar(bar);
    const float vT = __uint_as_float(spare[4]);
    const float vB = __uint_as_float(spare[5]);

    // ---- stats tail over compact list (float compares) ---------------------
#pragma unroll 1
    for (int i = 0; i < citers; i++) {
        unsigned idx = (unsigned)(i * 32 + lane);
        if (idx < cnt) {
            float v = __uint_as_float(rowU[eBase + idx]);
            if (v > vT) sg += v;
            if (v < vB) sl += v;
        }
    }
    sg = wredf(sg);
    sl = wredf(sl);

    float* accF = reinterpret_cast<float*>(spare + 8);
    if (lane == 0) {
        atomicAdd(&accF[0], sg);
        atomicAdd(&accF[1], sl);
    }
    chbar(bar);

    if (q == 0 && lane == 0) {
        int rT3  = (int)spare[6];
        int rbme = (int)spare[7];            // rB3 - eqB (signed)
        int cg   = KSEL - rT3;               // strictly > vT
        int cl   = HWN - RBRANK + rbme;      // strictly < vB
        float Sg = accF[0], Sl = accF[1];
        float xmax = (Sg + (float)(KSEL - cg) * vT) * (1.0f / (float)KSEL);
        float xmin = (Sl + (float)(KSEL - cl) * vB) * (ALPHA / (float)KSEL);
        out[b * NCH + c0 + w] = 0.5f * (xmax + xmin);
    }
}

extern "C" void kernel_launch(void* const* d_in, const int* in_sizes, int n_in,
                              void* d_out, int out_size)
{
    const float* x = (const float*)d_in[0];
    float* out = (float*)d_out;
    cudaFuncSetAttribute(wildcat_kernel,
                         cudaFuncAttributeMaxDynamicSharedMemorySize,
                         SMEM_WORDS * (int)sizeof(unsigned));
    wildcat_kernel<<<NBATCH * (NCH / CPB), 512, SMEM_WORDS * sizeof(unsigned)>>>(x, out);
}